// round 5
// baseline (speedup 1.0000x reference)
#include <cuda_runtime.h>
#include <math.h>

// MT 1D forward + loss, fused single kernel. Output: [total, loss_rhoa, loss_phase].
//
// Reflection-coefficient Moebius recursion (scale-invariant, divide-free):
//   w  = E*V,  U' = U - r*w,  V' = r*U - w
//   r  = (g-1)/(g+1), g = sqrt(rho_j/rho_{j-1})   (real, precomputed)
//   E  = exp(-a)*(cos a - i sin a),  a = s*coef_j, coef_j = t_j*sqrt(2*mu/rho_j)
// Loop is software-pipelined: per 8-step block, all E_j are computed first
// (independent MUFU/FMA stream), then the 8 dependent U,V updates (pure FFMA
// chain, depth ~16cyc/step) run while the next block's E-math issues.
// Final: x = N/D = (U+V)/(U-V); app_res = rho_0*|x|^2;
//   phase = atan2(A+B, A-B), A=Nr*Dr+Ni*Di, B=Ni*Dr-Nr*Di (no division).

#define MUF 1.25663706143591729e-6f   // 4*pi*1e-7
#define TWO_PI_F 6.2831853071795864f
#define RAD2DEG_F 57.295779513082321f

__device__ float2 g_part[256];
__device__ unsigned int g_ticket;     // zero-init; reset by last block each launch

__device__ __forceinline__ float frcp_fast(float x) {
    float r;
    asm("rcp.approx.ftz.f32 %0, %1;" : "=f"(r) : "f"(x));
    return r;
}

__global__ __launch_bounds__(128, 1)
void mt_fused(const float* __restrict__ res,
              const float* __restrict__ thick,
              const float* __restrict__ freq,
              const float* __restrict__ orhoa,
              const float* __restrict__ ophase,
              float* __restrict__ out,
              int nz, int nf, float inv_nf)
{
    __shared__ float2 lay[512];        // (coef_j, r_j), scan order (deepest first)
    __shared__ float  sc_x0, sc_lrho0;
    __shared__ float2 red[4];
    __shared__ int    is_last;

    const int nl  = nz - 1;
    const int tid = threadIdx.x;

    for (int i = tid; i < nl; i += blockDim.x) {
        int   j   = nl - 1 - i;                    // deepest first
        float rho = res[j];
        float t   = thick[j];
        float g   = (j >= 1) ? sqrtf(rho / res[j - 1]) : 1.0f;
        lay[i] = make_float2(t * sqrtf(2.0f * MUF / rho),
                             (g - 1.0f) / (g + 1.0f));
    }
    if (tid == 0) {
        sc_x0    = sqrtf(res[nz - 1] / res[nz - 2]);  // x_init (real)
        sc_lrho0 = log10f(res[0]);
    }
    __syncthreads();

    int   f  = blockIdx.x * blockDim.x + tid;
    float lr = 0.0f, lp = 0.0f;

    if (f < nf) {
        float omega = TWO_PI_F * freq[f];
        float s     = sqrtf(omega);

        float x0 = sc_x0;
        float Ur = x0 + 1.0f, Ui = 0.0f;
        float Vr = x0 - 1.0f, Vi = 0.0f;

        int i = 0;
        for (; i + 8 <= nl; i += 8) {
            // Phase A: independent E-math for the whole block (hides MUFU lat)
            float er[8], ei[8], rc[8];
            #pragma unroll
            for (int u = 0; u < 8; ++u) {
                float2 L = lay[i + u];
                float a  = s * L.x;
                float em = __expf(-a);
                float sa, ca;
                __sincosf(a, &sa, &ca);
                er[u] = em * ca;
                ei[u] = em * sa;
                rc[u] = L.y;
            }
            // Phase B: dependent updates (4 FFMA for w + 4 FFMA for U,V)
            #pragma unroll
            for (int u = 0; u < 8; ++u) {
                float wr = er[u] * Vr + ei[u] * Vi;     // w = E*V (E = er - i*ei)
                float wi = er[u] * Vi - ei[u] * Vr;
                float r  = rc[u];
                float nUr = fmaf(-r, wr, Ur);
                float nUi = fmaf(-r, wi, Ui);
                float nVr = fmaf( r, Ur, -wr);
                float nVi = fmaf( r, Ui, -wi);
                Ur = nUr; Ui = nUi; Vr = nVr; Vi = nVi;
            }
            // renormalize: |det|<1 per step => monotone shrink; ratio invariant
            float m = frcp_fast(fabsf(Ur) + fabsf(Ui));
            Ur *= m; Ui *= m; Vr *= m; Vi *= m;
        }
        for (; i < nl; ++i) {
            float2 L = lay[i];
            float a  = s * L.x;
            float em = __expf(-a);
            float sa, ca;
            __sincosf(a, &sa, &ca);
            float e_r = em * ca, e_i = em * sa;
            float wr = e_r * Vr + e_i * Vi;
            float wi = e_r * Vi - e_i * Vr;
            float r  = L.y;
            float nUr = fmaf(-r, wr, Ur);
            float nUi = fmaf(-r, wi, Ui);
            float nVr = fmaf( r, Ur, -wr);
            float nVi = fmaf( r, Ui, -wi);
            Ur = nUr; Ui = nUi; Vr = nVr; Vi = nVi;
        }

        float Nr = Ur + Vr, Ni = Ui + Vi;
        float Dr = Ur - Vr, Di = Ui - Vi;

        float n2 = fmaxf(Nr * Nr + Ni * Ni, 1e-30f);
        float d2 = fmaxf(Dr * Dr + Di * Di, 1e-30f);
        float A  = Nr * Dr + Ni * Di;
        float B  = Ni * Dr - Nr * Di;

        // app_res = rho0 * n2 / d2 ; Z ∝ (A-B) + i(A+B) (positive scale)
        float e1 = sc_lrho0 + log10f(n2) - log10f(d2) - log10f(orhoa[f]);
        float ph = atan2f(A + B, A - B) * RAD2DEG_F;
        float e2 = ph - ophase[f];
        lr = e1 * e1;
        lp = e2 * e2;
    }

    // deterministic block reduction (128 threads = 4 warps)
    const unsigned FULL = 0xffffffffu;
    #pragma unroll
    for (int o = 16; o > 0; o >>= 1) {
        lr += __shfl_down_sync(FULL, lr, o);
        lp += __shfl_down_sync(FULL, lp, o);
    }
    int wid = tid >> 5, lane = tid & 31;
    if (lane == 0) red[wid] = make_float2(lr, lp);
    __syncthreads();
    if (tid == 0) {
        float slr = red[0].x + red[1].x + red[2].x + red[3].x;
        float slp = red[0].y + red[1].y + red[2].y + red[3].y;
        g_part[blockIdx.x] = make_float2(slr, slp);
        __threadfence();
        unsigned t = atomicAdd(&g_ticket, 1u);
        is_last = (t == gridDim.x - 1) ? 1 : 0;
    }
    __syncthreads();

    if (is_last) {
        __threadfence();
        float flr = 0.0f, flp = 0.0f;
        if (tid < 32) {
            for (int i = tid; i < (int)gridDim.x; i += 32) {
                volatile float* vp = (volatile float*)&g_part[i];
                flr += vp[0];
                flp += vp[1];
            }
            #pragma unroll
            for (int o = 16; o > 0; o >>= 1) {
                flr += __shfl_down_sync(FULL, flr, o);
                flp += __shfl_down_sync(FULL, flp, o);
            }
            if (tid == 0) {
                float mlr = flr * inv_nf;
                float mlp = flp * inv_nf;
                out[0] = mlr + 10.0f * mlp;   // LAMBDA_RHOA=1, LAMBDA_PHASE=10
                out[1] = mlr;
                out[2] = mlp;
                g_ticket = 0;                 // reset for next graph replay
            }
        }
    }
}

extern "C" void kernel_launch(void* const* d_in, const int* in_sizes, int n_in,
                              void* d_out, int out_size)
{
    const float* res = (const float*)d_in[0];
    const float* th  = (const float*)d_in[1];
    const float* fr  = (const float*)d_in[2];
    const float* orh = (const float*)d_in[3];
    const float* oph = (const float*)d_in[4];
    int nz = in_sizes[0];
    int nf = in_sizes[2];

    const int threads = 128;
    int blocks = (nf + threads - 1) / threads;     // 128 for NF=16384
    if (blocks > 256) blocks = 256;

    mt_fused<<<blocks, threads>>>(res, th, fr, orh, oph,
                                  (float*)d_out, nz, nf, 1.0f / (float)nf);
}